// round 2
// baseline (speedup 1.0000x reference)
#include <cuda_runtime.h>
#include <math.h>

// Problem constants
#define BB 8
#define SS 1024
#define EE 512
#define HH 8
#define DD 64

// Scratch (static __device__ arrays — allocation-free per harness rules)
__device__ float g_qh[BB*HH*SS*DD];   // [B,H,S,D] 16 MB
__device__ float g_kh[BB*HH*SS*DD];
__device__ float g_vh[BB*HH*SS*DD];
__device__ float g_ao[BB*SS*EE];      // [B,S,E]   16 MB

__device__ __forceinline__ float warpMax(float v) {
    #pragma unroll
    for (int o = 16; o > 0; o >>= 1) v = fmaxf(v, __shfl_xor_sync(0xffffffffu, v, o));
    return v;
}
__device__ __forceinline__ float warpSum(float v) {
    #pragma unroll
    for (int o = 16; o > 0; o >>= 1) v += __shfl_xor_sync(0xffffffffu, v, o);
    return v;
}

// ============================================================================
// Projection GEMM: Y = X @ W^T + bias, X:[8192,512], W:[512,512] (row n = weights)
// Output scattered to [B,H,S,D] head layout. z selects (q,Wk),(k,Wk),(v,Wv).
// Tile 64x64, K-step 32, 256 threads, 4x4 microtile.
// ============================================================================
__global__ __launch_bounds__(256)
void proj_kernel(const float* __restrict__ q, const float* __restrict__ k,
                 const float* __restrict__ v,
                 const float* __restrict__ Wk, const float* __restrict__ bk,
                 const float* __restrict__ Wv, const float* __restrict__ bv)
{
    __shared__ float As[32][64];
    __shared__ float Bs[32][64];

    const int z = blockIdx.z;
    const float* X    = (z == 0) ? q : ((z == 1) ? k : v);
    const float* W    = (z == 2) ? Wv : Wk;
    const float* bias = (z == 2) ? bv : bk;
    float* Y = (z == 0) ? g_qh : ((z == 1) ? g_kh : g_vh);

    const int m0 = blockIdx.x * 64;
    const int n0 = blockIdx.y * 64;
    const int tid = threadIdx.x;
    const int tx = tid & 15;      // n dir (x4)
    const int ty = tid >> 4;      // m dir (x4)

    float acc[4][4] = {};

    for (int k0 = 0; k0 < 512; k0 += 32) {
        #pragma unroll
        for (int r = 0; r < 2; r++) {
            int idx = tid + r * 256;          // 0..511 float4 slots
            int mm  = idx >> 3;               // 0..63
            int kk  = (idx & 7) << 2;         // 0..28
            float4 av = *(const float4*)&X[(long)(m0 + mm) * 512 + k0 + kk];
            As[kk+0][mm] = av.x; As[kk+1][mm] = av.y;
            As[kk+2][mm] = av.z; As[kk+3][mm] = av.w;
            float4 wv = *(const float4*)&W[(long)(n0 + mm) * 512 + k0 + kk];
            Bs[kk+0][mm] = wv.x; Bs[kk+1][mm] = wv.y;
            Bs[kk+2][mm] = wv.z; Bs[kk+3][mm] = wv.w;
        }
        __syncthreads();
        #pragma unroll
        for (int kk = 0; kk < 32; kk++) {
            float4 bq = *(const float4*)&Bs[kk][tx * 4];
            float a0 = As[kk][ty*4+0], a1 = As[kk][ty*4+1];
            float a2 = As[kk][ty*4+2], a3 = As[kk][ty*4+3];
            acc[0][0] += a0*bq.x; acc[0][1] += a0*bq.y; acc[0][2] += a0*bq.z; acc[0][3] += a0*bq.w;
            acc[1][0] += a1*bq.x; acc[1][1] += a1*bq.y; acc[1][2] += a1*bq.z; acc[1][3] += a1*bq.w;
            acc[2][0] += a2*bq.x; acc[2][1] += a2*bq.y; acc[2][2] += a2*bq.z; acc[2][3] += a2*bq.w;
            acc[3][0] += a3*bq.x; acc[3][1] += a3*bq.y; acc[3][2] += a3*bq.z; acc[3][3] += a3*bq.w;
        }
        __syncthreads();
    }

    // Epilogue: bias + scatter to [B,H,S,D]. BN==64==D so n-tile == head h.
    const int h = blockIdx.y;
    float b0 = bias[n0 + tx*4 + 0], b1 = bias[n0 + tx*4 + 1];
    float b2 = bias[n0 + tx*4 + 2], b3 = bias[n0 + tx*4 + 3];
    #pragma unroll
    for (int i = 0; i < 4; i++) {
        int m = m0 + ty*4 + i;
        int bb = m >> 10;          // / S
        int s  = m & 1023;
        float4 o;
        o.x = acc[i][0] + b0; o.y = acc[i][1] + b1;
        o.z = acc[i][2] + b2; o.w = acc[i][3] + b3;
        *(float4*)&Y[((long)(bb*HH + h) * SS + s) * DD + tx*4] = o;
    }
}

// ============================================================================
// Output GEMM: out = ao @ Wo^T + bo  (direct [8192,512] layout)
// ============================================================================
__global__ __launch_bounds__(256)
void out_kernel(const float* __restrict__ Wo, const float* __restrict__ bo,
                float* __restrict__ out)
{
    __shared__ float As[32][64];
    __shared__ float Bs[32][64];

    const int m0 = blockIdx.x * 64;
    const int n0 = blockIdx.y * 64;
    const int tid = threadIdx.x;
    const int tx = tid & 15;
    const int ty = tid >> 4;

    float acc[4][4] = {};

    for (int k0 = 0; k0 < 512; k0 += 32) {
        #pragma unroll
        for (int r = 0; r < 2; r++) {
            int idx = tid + r * 256;
            int mm  = idx >> 3;
            int kk  = (idx & 7) << 2;
            float4 av = *(const float4*)&g_ao[(long)(m0 + mm) * 512 + k0 + kk];
            As[kk+0][mm] = av.x; As[kk+1][mm] = av.y;
            As[kk+2][mm] = av.z; As[kk+3][mm] = av.w;
            float4 wv = *(const float4*)&Wo[(long)(n0 + mm) * 512 + k0 + kk];
            Bs[kk+0][mm] = wv.x; Bs[kk+1][mm] = wv.y;
            Bs[kk+2][mm] = wv.z; Bs[kk+3][mm] = wv.w;
        }
        __syncthreads();
        #pragma unroll
        for (int kk = 0; kk < 32; kk++) {
            float4 bq = *(const float4*)&Bs[kk][tx * 4];
            float a0 = As[kk][ty*4+0], a1 = As[kk][ty*4+1];
            float a2 = As[kk][ty*4+2], a3 = As[kk][ty*4+3];
            acc[0][0] += a0*bq.x; acc[0][1] += a0*bq.y; acc[0][2] += a0*bq.z; acc[0][3] += a0*bq.w;
            acc[1][0] += a1*bq.x; acc[1][1] += a1*bq.y; acc[1][2] += a1*bq.z; acc[1][3] += a1*bq.w;
            acc[2][0] += a2*bq.x; acc[2][1] += a2*bq.y; acc[2][2] += a2*bq.z; acc[2][3] += a2*bq.w;
            acc[3][0] += a3*bq.x; acc[3][1] += a3*bq.y; acc[3][2] += a3*bq.z; acc[3][3] += a3*bq.w;
        }
        __syncthreads();
    }

    float b0 = bo[n0 + tx*4 + 0], b1 = bo[n0 + tx*4 + 1];
    float b2 = bo[n0 + tx*4 + 2], b3 = bo[n0 + tx*4 + 3];
    #pragma unroll
    for (int i = 0; i < 4; i++) {
        int m = m0 + ty*4 + i;
        float4 o;
        o.x = acc[i][0] + b0; o.y = acc[i][1] + b1;
        o.z = acc[i][2] + b2; o.w = acc[i][3] + b3;
        *(float4*)&out[(long)m * 512 + n0 + tx*4] = o;
    }
}

// ============================================================================
// Attention kernel: per CTA = (b, h, 32-query block).
// Full score rows live in SMEM so softmax -> cumsum -> decay -> softmax can
// run warp-locally (one warp owns 4 rows).
// Dynamic smem: qs[32][64] + kt[64][65] + sc[32][1024] = 155,904 B.
// ============================================================================
__global__ __launch_bounds__(256, 1)
void attn_kernel(const float* __restrict__ gammas)
{
    extern __shared__ float smem_[];
    float* qs = smem_;                 // [32][64]
    float* kt = smem_ + 32*64;         // [64][65] (padded: conflict-free col walk)
    float* sc = kt + 64*65;            // [32][1024]

    const int i0  = blockIdx.x * 32;
    const int h   = blockIdx.y;
    const int b   = blockIdx.z;
    const int tid = threadIdx.x;
    const int w    = tid >> 5;
    const int lane = tid & 31;

    const long base = (long)(b*HH + h) * SS;
    const float* Q = g_qh + base * DD;
    const float* K = g_kh + base * DD;
    const float* V = g_vh + base * DD;

    const float g = gammas[h];
    const float gamma = -log1pf(expf(g));   // -softplus(gamma_h)

    // Load Q tile: 32 rows x 64 = 512 float4 slots
    #pragma unroll
    for (int r = 0; r < 2; r++) {
        int idx = tid + r * 256;
        int row = idx >> 4;
        int dv  = (idx & 15) << 2;
        float4 t = *(const float4*)&Q[(long)(i0 + row) * DD + dv];
        *(float4*)&qs[row * DD + dv] = t;
    }

    const int ntiles = (i0 + 31) / 64 + 1;   // causal: only key tiles <= max row
    const int tend   = ntiles * 64;

    // -------- Phase A: scores = Q K^T / 8 --------
    for (int t = 0; t < ntiles; t++) {
        __syncthreads();
        // K tile: 64 rows x 64 = 1024 float4 slots -> 4 iterations of 256
        #pragma unroll
        for (int r = 0; r < 4; r++) {
            int idx = tid + r * 256;          // 0..1023
            int row = idx >> 4;               // 0..63
            int dv  = (idx & 15) << 2;        // 0..60
            float4 tv = *(const float4*)&K[(long)(t*64 + row) * DD + dv];
            kt[row*65 + dv+0] = tv.x; kt[row*65 + dv+1] = tv.y;
            kt[row*65 + dv+2] = tv.z; kt[row*65 + dv+3] = tv.w;
        }
        __syncthreads();

        float a0[4], a1[4];
        #pragma unroll
        for (int r = 0; r < 4; r++) { a0[r] = 0.f; a1[r] = 0.f; }
        #pragma unroll 8
        for (int d = 0; d < 64; d++) {
            float k0 = kt[lane*65 + d];
            float k1 = kt[(lane+32)*65 + d];
            #pragma unroll
            for (int r = 0; r < 4; r++) {
                float qv = qs[(w*4 + r)*64 + d];
                a0[r] += qv * k0;
                a1[r] += qv * k1;
            }
        }
        #pragma unroll
        for (int r = 0; r < 4; r++) {
            sc[(w*4+r)*1024 + t*64 + lane]      = a0[r] * 0.125f;
            sc[(w*4+r)*1024 + t*64 + lane + 32] = a1[r] * 0.125f;
        }
    }
    // warps only touch their own sc rows from here until Phase C's kt reuse

    // -------- Phase B: softmax -> suffix-scan decay -> softmax (warp/row) ---
    for (int r = 0; r < 4; r++) {
        const int i = i0 + w*4 + r;
        float* row = sc + (w*4 + r) * 1024;

        if (i == 0) {   // zero_pad: first query row's probs are all zero
            for (int j = lane; j < tend; j += 32) row[j] = 0.f;
            continue;
        }

        // softmax #1 (normalized sm; disttot == 1)
        float mx = -3.4e38f;
        for (int j = lane; j <= i; j += 32) mx = fmaxf(mx, row[j]);
        mx = warpMax(mx);
        float sum = 0.f;
        for (int j = lane; j <= i; j += 32) sum += __expf(row[j] - mx);
        sum = warpSum(sum);
        const float inv = 1.f / sum;

        // inclusive scan of sm; suffix = 1 - prefix; decay applied to scores
        float carry = 0.f;
        const int nch = (i >> 5) + 1;
        for (int c = 0; c < nch; c++) {
            int j = c*32 + lane;
            float sorig = (j <= i) ? row[j] : 0.f;
            float e = (j <= i) ? __expf(sorig - mx) * inv : 0.f;
            float incl = e;
            #pragma unroll
            for (int o = 1; o < 32; o <<= 1) {
                float t2 = __shfl_up_sync(0xffffffffu, incl, o);
                if (lane >= o) incl += t2;
            }
            float pref = carry + incl;
            carry = __shfl_sync(0xffffffffu, pref, 31);
            float suffix = 1.f - pref;
            float pos = (float)(i - j);
            float dist = sqrtf(fmaxf(suffix * pos, 0.f));
            float eff = __expf(dist * gamma);
            eff = fminf(fmaxf(eff, 1e-5f), 1e5f);
            if (j <= i) row[j] = sorig * eff;
        }

        // softmax #2
        float m2 = -3.4e38f;
        for (int j = lane; j <= i; j += 32) m2 = fmaxf(m2, row[j]);
        m2 = warpMax(m2);
        float s2 = 0.f;
        for (int j = lane; j <= i; j += 32) s2 += __expf(row[j] - m2);
        s2 = warpSum(s2);
        const float inv2 = 1.f / s2;
        for (int j = lane; j < tend; j += 32)
            row[j] = (j <= i) ? __expf(row[j] - m2) * inv2 : 0.f;
    }

    // -------- Phase C: out = P @ V --------
    float o0[4], o1[4];
    #pragma unroll
    for (int r = 0; r < 4; r++) { o0[r] = 0.f; o1[r] = 0.f; }

    for (int t = 0; t < ntiles; t++) {
        __syncthreads();    // all warps past Phase A/B before kt reuse
        // V tile: 64 rows x 64 = 1024 float4 slots -> 4 iterations
        #pragma unroll
        for (int r = 0; r < 4; r++) {
            int idx = tid + r * 256;
            int row = idx >> 4;
            int dv  = (idx & 15) << 2;
            float4 tv = *(const float4*)&V[(long)(t*64 + row) * DD + dv];
            kt[row*65 + dv+0] = tv.x; kt[row*65 + dv+1] = tv.y;
            kt[row*65 + dv+2] = tv.z; kt[row*65 + dv+3] = tv.w;
        }
        __syncthreads();
        #pragma unroll 8
        for (int jj = 0; jj < 64; jj++) {
            float v0 = kt[jj*65 + lane];
            float v1 = kt[jj*65 + lane + 32];
            #pragma unroll
            for (int r = 0; r < 4; r++) {
                float p = sc[(w*4+r)*1024 + t*64 + jj];
                o0[r] += p * v0;
                o1[r] += p * v1;
            }
        }
    }

    #pragma unroll
    for (int r = 0; r < 4; r++) {
        int s = i0 + w*4 + r;
        float* dst = g_ao + ((long)(b*SS + s)) * EE + h*DD;
        dst[lane]      = o0[r];
        dst[lane + 32] = o1[r];
    }
}

// ============================================================================
extern "C" void kernel_launch(void* const* d_in, const int* in_sizes, int n_in,
                              void* d_out, int out_size)
{
    const float* q      = (const float*)d_in[0];
    const float* k      = (const float*)d_in[1];
    const float* v      = (const float*)d_in[2];
    const float* Wk     = (const float*)d_in[3];
    const float* bk     = (const float*)d_in[4];
    const float* Wv     = (const float*)d_in[5];
    const float* bv     = (const float*)d_in[6];
    const float* Wo     = (const float*)d_in[7];
    const float* bo     = (const float*)d_in[8];
    const float* gammas = (const float*)d_in[9];
    float* out = (float*)d_out;

    const size_t shmem = (size_t)(32*64 + 64*65 + 32*1024) * sizeof(float); // 155,904
    cudaFuncSetAttribute(attn_kernel, cudaFuncAttributeMaxDynamicSharedMemorySize,
                         (int)shmem);

    proj_kernel<<<dim3(128, 8, 3), 256>>>(q, k, v, Wk, bk, Wv, bv);
    attn_kernel<<<dim3(SS/32, HH, BB), 256, shmem>>>(gammas);
    out_kernel<<<dim3(128, 8), 256>>>(Wo, bo, out);
}

// round 4
// speedup vs baseline: 1.5170x; 1.5170x over previous
#include <cuda_runtime.h>
#include <cuda_bf16.h>
#include <math.h>
#include <stdint.h>

#define BB 8
#define SS 1024
#define EE 512
#define HH 8
#define DD 64

// ---------------- scratch (__device__ globals; no allocation) ---------------
__device__ float g_qh[BB*HH*SS*DD];            // [B,H,S,D] fp32
__device__ float g_kh[BB*HH*SS*DD];
__device__ float g_vh[BB*HH*SS*DD];
__device__ __nv_bfloat16 g_xh[3L*8192*512];    // q,k,v bf16 hi
__device__ __nv_bfloat16 g_xl[3L*8192*512];    // q,k,v bf16 lo
__device__ __nv_bfloat16 g_wh[3L*512*512];     // Wk,Wv,Wo hi
__device__ __nv_bfloat16 g_wl[3L*512*512];     // Wk,Wv,Wo lo
__device__ __nv_bfloat16 g_aoh[8192L*512];     // attention out hi
__device__ __nv_bfloat16 g_aol[8192L*512];     // attention out lo

// ---------------- helpers ---------------------------------------------------
__device__ __forceinline__ uint32_t smem_u32(const void* p) {
    uint32_t a;
    asm("{ .reg .u64 t; cvta.to.shared.u64 t, %1; cvt.u32.u64 %0, t; }"
        : "=r"(a) : "l"(p));
    return a;
}
__device__ __forceinline__ void ldsm_x4(uint32_t r[4], uint32_t addr) {
    asm volatile("ldmatrix.sync.aligned.m8n8.x4.shared.b16 {%0,%1,%2,%3}, [%4];"
        : "=r"(r[0]), "=r"(r[1]), "=r"(r[2]), "=r"(r[3]) : "r"(addr));
}
__device__ __forceinline__ void ldsm_x2(uint32_t r[2], uint32_t addr) {
    asm volatile("ldmatrix.sync.aligned.m8n8.x2.shared.b16 {%0,%1}, [%2];"
        : "=r"(r[0]), "=r"(r[1]) : "r"(addr));
}
__device__ __forceinline__ void mma_bf16(float c[4], const uint32_t a[4],
                                         const uint32_t b[2]) {
    asm volatile(
        "mma.sync.aligned.m16n8k16.row.col.f32.bf16.bf16.f32 "
        "{%0,%1,%2,%3}, {%4,%5,%6,%7}, {%8,%9}, {%0,%1,%2,%3};"
        : "+f"(c[0]), "+f"(c[1]), "+f"(c[2]), "+f"(c[3])
        : "r"(a[0]), "r"(a[1]), "r"(a[2]), "r"(a[3]), "r"(b[0]), "r"(b[1]));
}
__device__ __forceinline__ float warpMax(float v) {
    #pragma unroll
    for (int o = 16; o > 0; o >>= 1) v = fmaxf(v, __shfl_xor_sync(0xffffffffu, v, o));
    return v;
}
__device__ __forceinline__ float warpSum(float v) {
    #pragma unroll
    for (int o = 16; o > 0; o >>= 1) v += __shfl_xor_sync(0xffffffffu, v, o);
    return v;
}

// ============================================================================
// Split kernel: fp32 -> bf16 (hi, lo) for q/k/v and Wk/Wv/Wo.
// ============================================================================
__global__ __launch_bounds__(256)
void split_kernel(const float* __restrict__ q, const float* __restrict__ k,
                  const float* __restrict__ v,
                  const float* __restrict__ Wk, const float* __restrict__ Wv,
                  const float* __restrict__ Wo)
{
    const long NX4 = 3L * 8192 * 512 / 4;    // 3,145,728
    const long NW4 = 3L * 512 * 512 / 4;     // 196,608
    long i4 = (long)blockIdx.x * blockDim.x + threadIdx.x;
    if (i4 >= NX4 + NW4) return;

    const float* src;
    __nv_bfloat16 *dh, *dl;
    long off4;
    if (i4 < NX4) {
        long z = i4 >> 20;                    // 8192*512/4 = 2^20
        off4 = i4 & ((1L << 20) - 1);
        src = (z == 0) ? q : ((z == 1) ? k : v);
        dh = g_xh + z * (8192L * 512);
        dl = g_xl + z * (8192L * 512);
    } else {
        long j4 = i4 - NX4;
        long w = j4 / 65536;                  // 512*512/4
        off4 = j4 - w * 65536;
        src = (w == 0) ? Wk : ((w == 1) ? Wv : Wo);
        dh = g_wh + w * (512L * 512);
        dl = g_wl + w * (512L * 512);
    }
    float4 x = *(const float4*)(src + off4 * 4);
    __nv_bfloat16 h0 = __float2bfloat16(x.x), h1 = __float2bfloat16(x.y);
    __nv_bfloat16 h2 = __float2bfloat16(x.z), h3 = __float2bfloat16(x.w);
    __nv_bfloat162 hp0(h0, h1), hp1(h2, h3);
    __nv_bfloat162 lp0(__float2bfloat16(x.x - __bfloat162float(h0)),
                       __float2bfloat16(x.y - __bfloat162float(h1)));
    __nv_bfloat162 lp1(__float2bfloat16(x.z - __bfloat162float(h2)),
                       __float2bfloat16(x.w - __bfloat162float(h3)));
    *(__nv_bfloat162*)(dh + off4 * 4)     = hp0;
    *(__nv_bfloat162*)(dh + off4 * 4 + 2) = hp1;
    *(__nv_bfloat162*)(dl + off4 * 4)     = lp0;
    *(__nv_bfloat162*)(dl + off4 * 4 + 2) = lp1;
}

// ============================================================================
// Tensor-core GEMM (3x bf16 split): C[128,128] = A @ B^T + bias
//   mode 0 (grid.z = z): A = split(q/k/v), B = split(Wk/Wk/Wv), C -> head layout
//   mode 1:              A = split(ao),    B = split(Wo),       C -> out
// SMEM: 4 tiles [128 rows][64 cols bf16], padded to 144 B/row = 18432 B each.
// ============================================================================
#define TPAD 144
#define TSZ  18432     // 128*144
#define GEMM_SMEM (4*TSZ)

__global__ __launch_bounds__(256, 1)
void gemm_bf16(const float* __restrict__ bk, const float* __restrict__ bv,
               const float* __restrict__ bo, float* __restrict__ out, int mode)
{
    extern __shared__ char sm[];
    const uint32_t sb = smem_u32(sm);
    const int tid = threadIdx.x;
    const int wid = tid >> 5;
    const int lane = tid & 31;

    const __nv_bfloat16 *Ah, *Al, *Bh, *Bl;
    const float* bias;
    float* Yh = 0;                 // mode 0 target (fp32 head layout)
    if (mode == 0) {
        int z = blockIdx.z;
        Ah = g_xh + z * (8192L * 512);
        Al = g_xl + z * (8192L * 512);
        long w = (z == 2) ? 1 : 0;
        Bh = g_wh + w * (512L * 512);
        Bl = g_wl + w * (512L * 512);
        bias = (z == 2) ? bv : bk;
        Yh = (z == 0) ? g_qh : ((z == 1) ? g_kh : g_vh);
    } else {
        Ah = g_aoh; Al = g_aol;
        Bh = g_wh + 2 * (512L * 512);
        Bl = g_wl + 2 * (512L * 512);
        bias = bo;
    }

    const int m0 = blockIdx.x * 128;
    const int n0 = blockIdx.y * 128;
    const int wm = (wid >> 2) * 64;     // warp M offset in tile (0/64)
    const int wn = (wid & 3) * 32;      // warp N offset (0/32/64/96)

    const uint32_t sA_h = sb;
    const uint32_t sA_l = sb + TSZ;
    const uint32_t sB_h = sb + 2*TSZ;
    const uint32_t sB_l = sb + 3*TSZ;

    float c[4][4][4];
    #pragma unroll
    for (int a = 0; a < 4; a++)
        #pragma unroll
        for (int b = 0; b < 4; b++)
            #pragma unroll
            for (int d = 0; d < 4; d++) c[a][b][d] = 0.f;

    for (int ch = 0; ch < 8; ch++) {
        __syncthreads();
        // copy 4 tiles of [128][64] bf16 (16B per thread-iter)
        #pragma unroll
        for (int i = 0; i < 16; i++) {
            int slot = tid + i * 256;            // 0..4095
            int arr  = slot >> 10;               // 0:Ah 1:Al 2:Bh 3:Bl
            int r    = (slot >> 3) & 127;
            int cg   = slot & 7;
            const __nv_bfloat16* src =
                (arr == 0) ? Ah : ((arr == 1) ? Al : ((arr == 2) ? Bh : Bl));
            int grow = ((arr < 2) ? m0 : n0) + r;
            uint4 vdat = *(const uint4*)(src + (long)grow * 512 + ch * 64 + cg * 8);
            *(uint4*)(sm + arr * TSZ + r * TPAD + cg * 16) = vdat;
        }
        __syncthreads();

        #pragma unroll
        for (int ks = 0; ks < 4; ks++) {
            uint32_t bh[4][2], bl[4][2];
            #pragma unroll
            for (int ni = 0; ni < 4; ni++) {
                uint32_t addr = (uint32_t)((wn + ni*8 + (lane & 7)) * TPAD
                               + (ks*16 + ((lane >> 3) & 1) * 8) * 2);
                ldsm_x2(bh[ni], sB_h + addr);
                ldsm_x2(bl[ni], sB_l + addr);
            }
            #pragma unroll
            for (int mi = 0; mi < 4; mi++) {
                uint32_t addr = (uint32_t)((wm + mi*16 + (lane & 15)) * TPAD
                               + (ks*16 + (lane >> 4) * 8) * 2);
                uint32_t ah[4], al[4];
                ldsm_x4(ah, sA_h + addr);
                ldsm_x4(al, sA_l + addr);
                #pragma unroll
                for (int ni = 0; ni < 4; ni++) {
                    mma_bf16(c[mi][ni], ah, bh[ni]);
                    mma_bf16(c[mi][ni], ah, bl[ni]);
                    mma_bf16(c[mi][ni], al, bh[ni]);
                }
            }
        }
    }

    // Epilogue: c regs -> gmem (+bias). reg pair 0/1 row q, pair 2/3 row q+8.
    const int qrow = lane >> 2;
    const int qcol = (lane & 3) * 2;
    #pragma unroll
    for (int mi = 0; mi < 4; mi++) {
        #pragma unroll
        for (int ni = 0; ni < 4; ni++) {
            #pragma unroll
            for (int half = 0; half < 2; half++) {
                int m  = m0 + wm + mi*16 + qrow + half*8;
                int cn = n0 + wn + ni*8 + qcol;
                float2 o;
                o.x = c[mi][ni][half*2 + 0] + bias[cn];
                o.y = c[mi][ni][half*2 + 1] + bias[cn + 1];
                if (mode == 0) {
                    int b = m >> 10, s = m & 1023;
                    int h = cn >> 6, d = cn & 63;
                    *(float2*)&Yh[(((long)(b*HH + h)) * SS + s) * DD + d] = o;
                } else {
                    *(float2*)&out[(long)m * 512 + cn] = o;
                }
            }
        }
    }
}

// ============================================================================
// Attention kernel: per CTA = (b, h, 32-query block). (SIMT fp32)
// smem: qs[32][64] + kt[64][68] + sc[32][1024]
// ============================================================================
__global__ __launch_bounds__(256, 1)
void attn_kernel(const float* __restrict__ gammas)
{
    extern __shared__ float smem_[];
    float* qs = smem_;                 // [32][64]
    float* kt = smem_ + 32*64;         // [64][68]
    float* sc = kt + 64*68;            // [32][1024]

    const int i0  = blockIdx.x * 32;
    const int h   = blockIdx.y;
    const int b   = blockIdx.z;
    const int tid = threadIdx.x;
    const int w    = tid >> 5;
    const int lane = tid & 31;

    const long base = (long)(b*HH + h) * SS;
    const float* Q = g_qh + base * DD;
    const float* K = g_kh + base * DD;
    const float* V = g_vh + base * DD;

    const float g = gammas[h];
    const float gamma = -log1pf(expf(g));   // -softplus(gamma_h)

    #pragma unroll
    for (int r = 0; r < 2; r++) {
        int idx = tid + r * 256;
        int row = idx >> 4;
        int dv  = (idx & 15) << 2;
        float4 t = *(const float4*)&Q[(long)(i0 + row) * DD + dv];
        *(float4*)&qs[row * DD + dv] = t;
    }

    const int ntiles = (i0 + 31) / 64 + 1;
    const int tend   = ntiles * 64;

    // -------- Phase A: scores = Q K^T / 8 --------
    for (int t = 0; t < ntiles; t++) {
        __syncthreads();
        #pragma unroll
        for (int r = 0; r < 4; r++) {
            int idx = tid + r * 256;
            int row = idx >> 4;
            int dv  = (idx & 15) << 2;
            float4 tv = *(const float4*)&K[(long)(t*64 + row) * DD + dv];
            *(float4*)&kt[row*68 + dv] = tv;
        }
        __syncthreads();

        float a0[4] = {}, a1[4] = {};
        #pragma unroll
        for (int d4 = 0; d4 < 64; d4 += 4) {
            float4 k0 = *(const float4*)&kt[lane*68 + d4];
            float4 k1 = *(const float4*)&kt[(lane+32)*68 + d4];
            #pragma unroll
            for (int r = 0; r < 4; r++) {
                float4 qv = *(const float4*)&qs[(w*4 + r)*64 + d4];
                a0[r] = fmaf(qv.x, k0.x, fmaf(qv.y, k0.y,
                         fmaf(qv.z, k0.z, fmaf(qv.w, k0.w, a0[r]))));
                a1[r] = fmaf(qv.x, k1.x, fmaf(qv.y, k1.y,
                         fmaf(qv.z, k1.z, fmaf(qv.w, k1.w, a1[r]))));
            }
        }
        #pragma unroll
        for (int r = 0; r < 4; r++) {
            sc[(w*4+r)*1024 + t*64 + lane]      = a0[r] * 0.125f;
            sc[(w*4+r)*1024 + t*64 + lane + 32] = a1[r] * 0.125f;
        }
    }

    // -------- Phase B: softmax -> suffix-scan decay -> softmax --------------
    for (int r = 0; r < 4; r++) {
        const int i = i0 + w*4 + r;
        float* row = sc + (w*4 + r) * 1024;

        if (i == 0) {
            for (int j = lane; j < tend; j += 32) row[j] = 0.f;
            continue;
        }

        float mx = -3.4e38f;
        for (int j = lane; j <= i; j += 32) mx = fmaxf(mx, row[j]);
        mx = warpMax(mx);
        float sum = 0.f;
        for (int j = lane; j <= i; j += 32) sum += __expf(row[j] - mx);
        sum = warpSum(sum);
        const float inv = 1.f / sum;

        float carry = 0.f;
        const int nch = (i >> 5) + 1;
        for (int ccc = 0; ccc < nch; ccc++) {
            int j = ccc*32 + lane;
            float sorig = (j <= i) ? row[j] : 0.f;
            float e = (j <= i) ? __expf(sorig - mx) * inv : 0.f;
            float incl = e;
            #pragma unroll
            for (int o = 1; o < 32; o <<= 1) {
                float t2 = __shfl_up_sync(0xffffffffu, incl, o);
                if (lane >= o) incl += t2;
            }
            float pref = carry + incl;
            carry = __shfl_sync(0xffffffffu, pref, 31);
            float suffix = 1.f - pref;
            float pos = (float)(i - j);
            float dist = sqrtf(fmaxf(suffix * pos, 0.f));
            float eff = __expf(dist * gamma);
            eff = fminf(fmaxf(eff, 1e-5f), 1e5f);
            if (j <= i) row[j] = sorig * eff;
        }

        float m2 = -3.4e38f;
        for (int j = lane; j <= i; j += 32) m2 = fmaxf(m2, row[j]);
        m2 = warpMax(m2);
        float s2 = 0.f;
        for (int j = lane; j <= i; j += 32) s2 += __expf(row[j] - m2);
        s2 = warpSum(s2);
        const float inv2 = 1.f / s2;
        for (int j = lane; j < tend; j += 32)
            row[j] = (j <= i) ? __expf(row[j] - m2) * inv2 : 0.f;
    }

    // -------- Phase C: out = P @ V --------
    float o0[4] = {}, o1[4] = {};

    for (int t = 0; t < ntiles; t++) {
        __syncthreads();
        #pragma unroll
        for (int r = 0; r < 4; r++) {
            int idx = tid + r * 256;
            int row = idx >> 4;
            int dv  = (idx & 15) << 2;
            float4 tv = *(const float4*)&V[(long)(t*64 + row) * DD + dv];
            *(float4*)&kt[row*68 + dv] = tv;
        }
        __syncthreads();
        #pragma unroll 4
        for (int jj = 0; jj < 64; jj += 4) {
            float v0[4], v1[4];
            #pragma unroll
            for (int u = 0; u < 4; u++) {
                v0[u] = kt[(jj+u)*68 + lane];
                v1[u] = kt[(jj+u)*68 + lane + 32];
            }
            #pragma unroll
            for (int r = 0; r < 4; r++) {
                float4 p = *(const float4*)&sc[(w*4+r)*1024 + t*64 + jj];
                o0[r] = fmaf(p.x, v0[0], fmaf(p.y, v0[1],
                         fmaf(p.z, v0[2], fmaf(p.w, v0[3], o0[r]))));
                o1[r] = fmaf(p.x, v1[0], fmaf(p.y, v1[1],
                         fmaf(p.z, v1[2], fmaf(p.w, v1[3], o1[r]))));
            }
        }
    }

    // epilogue: write bf16 hi/lo for the out-projection GEMM
    #pragma unroll
    for (int r = 0; r < 4; r++) {
        int s = i0 + w*4 + r;
        long o = ((long)(b*SS + s)) * EE + h*DD;
        __nv_bfloat16 h0 = __float2bfloat16(o0[r]);
        __nv_bfloat16 h1 = __float2bfloat16(o1[r]);
        g_aoh[o + lane]      = h0;
        g_aoh[o + lane + 32] = h1;
        g_aol[o + lane]      = __float2bfloat16(o0[r] - __bfloat162float(h0));
        g_aol[o + lane + 32] = __float2bfloat16(o1[r] - __bfloat162float(h1));
    }
}

// ============================================================================
extern "C" void kernel_launch(void* const* d_in, const int* in_sizes, int n_in,
                              void* d_out, int out_size)
{
    const float* q      = (const float*)d_in[0];
    const float* k      = (const float*)d_in[1];
    const float* v      = (const float*)d_in[2];
    const float* Wk     = (const float*)d_in[3];
    const float* bk     = (const float*)d_in[4];
    const float* Wv     = (const float*)d_in[5];
    const float* bv     = (const float*)d_in[6];
    const float* Wo     = (const float*)d_in[7];
    const float* bo     = (const float*)d_in[8];
    const float* gammas = (const float*)d_in[9];
    float* out = (float*)d_out;

    const size_t attn_shmem = (size_t)(32*64 + 64*68 + 32*1024) * sizeof(float);
    cudaFuncSetAttribute(attn_kernel, cudaFuncAttributeMaxDynamicSharedMemorySize,
                         (int)attn_shmem);
    cudaFuncSetAttribute(gemm_bf16, cudaFuncAttributeMaxDynamicSharedMemorySize,
                         GEMM_SMEM);

    const long total4 = 3L*8192*512/4 + 3L*512*512/4;
    split_kernel<<<(int)((total4 + 255) / 256), 256>>>(q, k, v, Wk, Wv, Wo);
    gemm_bf16<<<dim3(64, 4, 3), 256, GEMM_SMEM>>>(bk, bv, bo, out, 0);
    attn_kernel<<<dim3(SS/32, HH, BB), 256, attn_shmem>>>(gammas);
    gemm_bf16<<<dim3(64, 4, 1), 256, GEMM_SMEM>>>(bk, bv, bo, out, 1);
}